// round 12
// baseline (speedup 1.0000x reference)
#include <cuda_runtime.h>
#include <cstdint>

// Problem constants (fixed by the dataset)
#define BV 4
#define KV 8
#define NV 4096
#define DV 64
#define NC 256
#define NBLK 128     // 32 blocks/batch; 1 CTA/SM -> all resident, spin barrier safe
#define NTHR 512
#define QPB 128      // pixels owned per block

// Swizzled row layout: row c holds 16 float4 slots; logical d-slot (d>>2) is
// stored at slot (d>>2)^(c&15). Column reads (fixed d, c=lane+32i) hit bank
// ((slot<<2)+(d&3))&31 -> exactly 2-way conflicts. Float4 ops everywhere.
#define SLOT_OFF(c, dg) (((c) << 6) + ((((dg) ^ ((c) & 15))) << 2))

// Shared layout (float offsets)
#define SM_VT    0                       // float[16384]
#define SM_TAB   16384                   // float[16384]
#define SM_HALF  32768                   // float[512]: two half-sums of counts
#define SM_CNTI  33280                   // int[256] local histogram
#define SM_CODE  33536                   // int[QPB]
#define SM_PC    33664                   // uint[NTHR]
#define SM_FLAG  34176                   // int[1]
#define SMEM_FLOATS 34180
#define SMEM_BYTES  (SMEM_FLOATS * 4)

// Global scratch: fully OVERWRITTEN each launch (replay-idempotent).
__device__ float g_part[NBLK * NC];
__device__ unsigned int          g_bcnt[BV] = {};
__device__ volatile unsigned int g_bgen[BV] = {};

// 8-bit hypercube transform (scalar): out[c] = sum_c' in[c'] * r^popc(c^c').
__device__ __forceinline__ void butterfly8(float g[8], float r) {
    #pragma unroll
    for (int k = 0; k < 5; k++) {
        #pragma unroll
        for (int i = 0; i < 8; i++) {
            float p = __shfl_xor_sync(0xFFFFFFFFu, g[i], 1 << k);
            g[i] = fmaf(r, p, g[i]);
        }
    }
    #pragma unroll
    for (int k = 0; k < 3; k++) {
        const int m = 1 << k;
        #pragma unroll
        for (int i = 0; i < 8; i++)
            if (!(i & m)) {
                const int j = i | m;
                const float a = g[i], b = g[j];
                g[i] = fmaf(r, b, a);
                g[j] = fmaf(r, a, b);
            }
    }
}

// Same transform applied to 4 independent columns packed as float4.
__device__ __forceinline__ void butterfly8v(float4 g[8], float r) {
    #pragma unroll
    for (int k = 0; k < 5; k++) {
        #pragma unroll
        for (int i = 0; i < 8; i++) {
            float4 p;
            p.x = __shfl_xor_sync(0xFFFFFFFFu, g[i].x, 1 << k);
            p.y = __shfl_xor_sync(0xFFFFFFFFu, g[i].y, 1 << k);
            p.z = __shfl_xor_sync(0xFFFFFFFFu, g[i].z, 1 << k);
            p.w = __shfl_xor_sync(0xFFFFFFFFu, g[i].w, 1 << k);
            g[i].x = fmaf(r, p.x, g[i].x); g[i].y = fmaf(r, p.y, g[i].y);
            g[i].z = fmaf(r, p.z, g[i].z); g[i].w = fmaf(r, p.w, g[i].w);
        }
    }
    #pragma unroll
    for (int k = 0; k < 3; k++) {
        const int m = 1 << k;
        #pragma unroll
        for (int i = 0; i < 8; i++)
            if (!(i & m)) {
                const int j = i | m;
                const float4 a = g[i], b = g[j];
                g[i].x = fmaf(r, b.x, a.x); g[j].x = fmaf(r, a.x, b.x);
                g[i].y = fmaf(r, b.y, a.y); g[j].y = fmaf(r, a.y, b.y);
                g[i].z = fmaf(r, b.z, a.z); g[j].z = fmaf(r, a.z, b.z);
                g[i].w = fmaf(r, b.w, a.w); g[j].w = fmaf(r, a.w, b.w);
            }
    }
}

__device__ __forceinline__ float f4c(float4 v, int j) {
    switch (j) { case 0: return v.x; case 1: return v.y; case 2: return v.z; }
    return v.w;
}

__global__ void __launch_bounds__(NTHR, 1) gda_kernel(
    const float* __restrict__ z, const uint8_t* __restrict__ em,
    const float* __restrict__ temp_p, const float* __restrict__ vt,
    float* __restrict__ out)
{
    extern __shared__ float smem[];
    float* s_vt   = smem + SM_VT;
    float* s_tab  = smem + SM_TAB;
    float* s_half = smem + SM_HALF;
    int*   s_cnti = (int*)(smem + SM_CNTI);
    int*   s_code = (int*)(smem + SM_CODE);
    unsigned int* s_pc = (unsigned int*)(smem + SM_PC);
    int*   s_flag = (int*)(smem + SM_FLAG);

    const int tid   = threadIdx.x;
    const int b     = blockIdx.x >> 5;
    const int qbase = (blockIdx.x & 31) << 7;

    if (tid < NC) s_cnti[tid] = 0;

    // ---- Probe em element width from a fixed 512B window (warp 0) ----
    // int32(0/1,LE): nonzero bytes only at offsets %4==0. byte layout with
    // ~256 random set bits in 512B: some misaligned byte nonzero w.p. ~1.
    if (tid < 32) {
        uint4 v = ((const uint4*)em)[tid];          // in-bounds either layout
        unsigned w[4] = {v.x, v.y, v.z, v.w};
        bool other = false, aligned = false;
        #pragma unroll
        for (int j = 0; j < 4; j++) {
            other   |= (w[j] & 0xFFFFFF00u) != 0u;
            aligned |= (w[j] & 0x000000FFu) != 0u;
        }
        unsigned bo = __ballot_sync(0xFFFFFFFFu, other);
        unsigned ba = __ballot_sync(0xFFFFFFFFu, aligned);
        if (tid == 0) s_flag[0] = (bo == 0u && ba != 0u) ? 1 : 0;
    }

    // ---- Codes: 4 threads/pixel, 2 bit-planes each (coalesced 512B) ----
    {
        const float* zb = z + ((size_t)b * KV) * NV + qbase;
        const int p  = tid & (QPB - 1);
        const int k0 = (tid >> 7) << 1;             // 0,2,4,6
        unsigned pc = (unsigned)(zb[k0 * NV + p]       > 0.5f) << k0
                    | (unsigned)(zb[(k0 + 1) * NV + p] > 0.5f) << (k0 + 1);
        s_pc[tid] = pc;
    }

    // ---- Stage vt (64KB) into swizzled smem: float4 loads AND stores ----
    {
        const float4* vt4 = (const float4*)vt;
        #pragma unroll
        for (int i = 0; i < 8; i++) {
            const int idx = tid + (i << 9);         // 0..4095 float4s
            float4 v = vt4[idx];
            const int c = idx >> 4, s4 = idx & 15;
            *(float4*)&s_vt[SLOT_OFF(c, s4)] = v;
        }
    }
    __syncthreads();

    // ---- Combine code bits, masked local histogram ----
    const bool is_i32 = (s_flag[0] != 0);
    if (tid < QPB) {
        const int code = (int)(s_pc[tid] | s_pc[tid + 128] |
                               s_pc[tid + 256] | s_pc[tid + 384]);
        s_code[tid] = code;
        const size_t mi = (size_t)(b * NV + qbase + tid) * (is_i32 ? 4 : 1);
        if (em[mi] != 0) atomicAdd(&s_cnti[code], 1);
    }
    __syncthreads();

    // ---- Publish complete partial histogram (overwrite -> idempotent) ----
    if (tid < NC)
        g_part[(blockIdx.x << 8) + tid] = (float)s_cnti[tid];

    // ---- Per-batch barrier (32-way) ----
    __syncthreads();
    if (tid == 0) {
        __threadfence();                            // release partials
        unsigned int g = g_bgen[b];
        if (atomicAdd(&g_bcnt[b], 1u) == 31u) {
            g_bcnt[b] = 0;
            __threadfence();
            g_bgen[b] = g + 1;
        } else {
            while (g_bgen[b] == g) { }
        }
        __threadfence();                            // acquire
    }
    __syncthreads();

    // ---- Sum the 32 partials: all 512 threads, two halves of 16 ----
    {
        const int col = tid & 255, half = tid >> 8;
        const float* gp = g_part + ((b << 5) << 8) + (half << 12) + col;
        float s = 0.0f;
        #pragma unroll
        for (int j = 0; j < 16; j++) s += __ldcg(gp + (j << 8));
        s_half[(half << 8) + col] = s;
    }
    __syncthreads();

    // ---- Table: warp w owns d = 4w..4w+3, all 4 columns as one float4 ----
    {
        const float temp = fmaxf(temp_p[0], 0.1f);
        const float r = expf(-1.0f / temp);
        const int lane = tid & 31, dg = tid >> 5;   // dg in 0..15

        float cnt[8], den[8], inv[8];
        #pragma unroll
        for (int i = 0; i < 8; i++) {
            const int c = lane + (i << 5);
            cnt[i] = s_half[c] + s_half[c + 256];
            den[i] = cnt[i];
        }
        butterfly8(den, r);
        #pragma unroll
        for (int i = 0; i < 8; i++) inv[i] = (den[i] > 0.0f) ? (1.0f / den[i]) : 0.0f;

        float4 g[8];
        #pragma unroll
        for (int i = 0; i < 8; i++) {
            const int c = lane + (i << 5);
            float4 v = *(const float4*)&s_vt[SLOT_OFF(c, dg)];
            g[i].x = v.x * cnt[i]; g[i].y = v.y * cnt[i];
            g[i].z = v.z * cnt[i]; g[i].w = v.w * cnt[i];
        }
        butterfly8v(g, r);
        #pragma unroll
        for (int i = 0; i < 8; i++) {
            const int c = lane + (i << 5);
            float4 o;
            o.x = g[i].x * inv[i]; o.y = g[i].y * inv[i];
            o.z = g[i].z * inv[i]; o.w = g[i].w * inv[i];
            *(float4*)&s_tab[SLOT_OFF(c, dg)] = o;
        }
    }
    __syncthreads();

    // ---- Output: 4 pixels x 4 d per thread; float4 LDS + register transpose ----
    {
        const int q4 = (tid & 31) << 2;             // 4 consecutive pixels
        const int dg = tid >> 5;                    // warp-uniform: d = 4*dg + j
        const int c0 = s_code[q4],     c1 = s_code[q4 + 1];
        const int c2 = s_code[q4 + 2], c3 = s_code[q4 + 3];
        const float4 t0 = *(const float4*)&s_tab[SLOT_OFF(c0, dg)];
        const float4 t1 = *(const float4*)&s_tab[SLOT_OFF(c1, dg)];
        const float4 t2 = *(const float4*)&s_tab[SLOT_OFF(c2, dg)];
        const float4 t3 = *(const float4*)&s_tab[SLOT_OFF(c3, dg)];
        float* ob = out + (((size_t)b * DV) << 12) + qbase + q4;
        #pragma unroll
        for (int j = 0; j < 4; j++) {
            const int d = (dg << 2) + j;
            float4 v = make_float4(f4c(t0, j), f4c(t1, j), f4c(t2, j), f4c(t3, j));
            *(float4*)(ob + ((size_t)d << 12)) = v;
        }
    }
}

extern "C" void kernel_launch(void* const* d_in, const int* in_sizes, int n_in,
                              void* d_out, int out_size) {
    const float*   z    = (const float*)d_in[0];
    const uint8_t* em   = (const uint8_t*)d_in[1];
    const float*   temp = (const float*)d_in[2];
    const float*   vt   = (const float*)d_in[3];
    // d_in[4] = mask_value: multiplied by attn==0 at unmasked keys -> never contributes.
    // d_in[5] = pop_lut: replaced by r^popc tensor-product transform.
    float* out = (float*)d_out;

    // Host-side attribute set, executes immediately; first applied on the
    // pre-capture correctness call, so graph capture is unaffected.
    cudaFuncSetAttribute(gda_kernel, cudaFuncAttributeMaxDynamicSharedMemorySize, SMEM_BYTES);

    gda_kernel<<<NBLK, NTHR, SMEM_BYTES>>>(z, em, temp, vt, out);
}

// round 13
// speedup vs baseline: 1.0455x; 1.0455x over previous
#include <cuda_runtime.h>
#include <cstdint>

// Problem constants (fixed by the dataset)
#define BV 4
#define KV 8
#define NV 4096
#define DV 64
#define NC 256
#define NBLK 128     // 32 blocks/batch; 1 CTA/SM -> all resident, spin barrier safe
#define NTHR 1024
#define QPB 128      // pixels owned per block
#define PAD 65       // s_tab row stride: butterfly stores conflict-free

// Shared layout (float offsets)
#define SM_TAB   0                          // float[256*65] = 16640
#define SM_CNT   16640                      // float[256] final counts
#define SM_Q     16896                      // float[1024] quarter partial sums
#define SM_CNTI  17920                      // int[256] local histogram
#define SM_CODE  18176                      // int[QPB]
#define SM_PC    18304                      // uint[NTHR]
#define SM_FLAG  19328                      // int[1]
#define SMEM_FLOATS 19332
#define SMEM_BYTES  (SMEM_FLOATS * 4)

// Global scratch: fully OVERWRITTEN each launch (replay-idempotent).
__device__ float g_part[NBLK * NC];
__device__ unsigned int          g_bcnt[BV] = {};
__device__ volatile unsigned int g_bgen[BV] = {};

// 8-bit hypercube transform: out[c] = sum_c' in[c'] * r^popc(c^c').
// Element c at lane (c&31), register (c>>5). Bits 0-4 cross-lane, 5-7 cross-reg.
__device__ __forceinline__ void butterfly8(float g[8], float r) {
    #pragma unroll
    for (int k = 0; k < 5; k++) {
        #pragma unroll
        for (int i = 0; i < 8; i++) {
            float p = __shfl_xor_sync(0xFFFFFFFFu, g[i], 1 << k);
            g[i] = fmaf(r, p, g[i]);
        }
    }
    #pragma unroll
    for (int k = 0; k < 3; k++) {
        const int m = 1 << k;
        #pragma unroll
        for (int i = 0; i < 8; i++)
            if (!(i & m)) {
                const int j = i | m;
                const float a = g[i], b = g[j];
                g[i] = fmaf(r, b, a);
                g[j] = fmaf(r, a, b);
            }
    }
}

__global__ void __launch_bounds__(NTHR, 1) gda_kernel(
    const float* __restrict__ z, const uint8_t* __restrict__ em,
    const float* __restrict__ temp_p, const float* __restrict__ vt,
    float* __restrict__ out)
{
    extern __shared__ float smem[];
    float* s_tab  = smem + SM_TAB;
    float* s_cnt  = smem + SM_CNT;
    float* s_q    = smem + SM_Q;
    int*   s_cnti = (int*)(smem + SM_CNTI);
    int*   s_code = (int*)(smem + SM_CODE);
    unsigned int* s_pc = (unsigned int*)(smem + SM_PC);
    int*   s_flag = (int*)(smem + SM_FLAG);

    const int tid   = threadIdx.x;
    const int b     = blockIdx.x >> 5;
    const int qbase = (blockIdx.x & 31) << 7;
    const int lane  = tid & 31, warp = tid >> 5;

    if (tid < NC) s_cnti[tid] = 0;

    // ---- Probe em element width from a fixed 512B window (warp 0) ----
    // int32(0/1,LE): nonzero bytes only at offsets %4==0. byte layout with
    // ~256 random set bits in 512B: some misaligned byte nonzero w.p. ~1.
    if (tid < 32) {
        uint4 v = ((const uint4*)em)[tid];          // in-bounds either layout
        unsigned w[4] = {v.x, v.y, v.z, v.w};
        bool other = false, aligned = false;
        #pragma unroll
        for (int j = 0; j < 4; j++) {
            other   |= (w[j] & 0xFFFFFF00u) != 0u;
            aligned |= (w[j] & 0x000000FFu) != 0u;
        }
        unsigned bo = __ballot_sync(0xFFFFFFFFu, other);
        unsigned ba = __ballot_sync(0xFFFFFFFFu, aligned);
        if (tid == 0) s_flag[0] = (bo == 0u && ba != 0u) ? 1 : 0;
    }

    // ---- Codes: 8 threads/pixel, 1 bit-plane each (fully coalesced) ----
    {
        const int p = tid & (QPB - 1);
        const int k = tid >> 7;                     // 0..7
        const float zv = z[((size_t)(b * KV + k) << 12) + qbase + p];
        s_pc[tid] = (unsigned)(zv > 0.5f) << k;
    }
    __syncthreads();

    // ---- Combine code bits, masked local histogram (128 threads) ----
    const bool is_i32 = (s_flag[0] != 0);
    if (tid < QPB) {
        unsigned code = 0;
        #pragma unroll
        for (int j = 0; j < 8; j++) code |= s_pc[tid + (j << 7)];
        s_code[tid] = (int)code;
        const size_t mi = (size_t)(b * NV + qbase + tid) * (is_i32 ? 4 : 1);
        if (em[mi] != 0) atomicAdd(&s_cnti[code], 1);
    }
    __syncthreads();

    // ---- Publish complete partial histogram (overwrite -> idempotent) ----
    if (tid < NC)
        g_part[(blockIdx.x << 8) + tid] = (float)s_cnti[tid];
    __syncthreads();

    // ---- Barrier ARRIVE only (release partials first) ----
    unsigned int bar_tok = 0;
    if (tid == 0) {
        __threadfence();
        bar_tok = g_bgen[b];
        if (atomicAdd(&g_bcnt[b], 1u) == 31u) {
            g_bcnt[b] = 0;
            __threadfence();
            g_bgen[b] = bar_tok + 1;
        }
    }

    // ---- Prefetch vt for MY butterfly columns while the barrier drains ----
    // warp owns d = 2*warp, 2*warp+1; needs vt[c][d0:d1] for c = lane+32i.
    float2 vpre[8];
    {
        const float2* vt2 = (const float2*)vt;      // vt[c*64 + 2*warp]
        #pragma unroll
        for (int i = 0; i < 8; i++)
            vpre[i] = __ldg(&vt2[((lane + (i << 5)) << 5) + warp]);
    }

    // ---- Barrier WAIT (vt loads in flight underneath) ----
    if (tid == 0) {
        while (g_bgen[b] == bar_tok) { }
        __threadfence();
    }
    __syncthreads();

    // ---- Sum 32 partials: 4 quarters of 8 (MLP=8), then combine ----
    {
        const int col = tid & 255, qtr = tid >> 8;
        const float* gp = g_part + (((b << 5) + (qtr << 3)) << 8) + col;
        float s = 0.0f;
        #pragma unroll
        for (int j = 0; j < 8; j++) s += __ldcg(gp + (j << 8));
        s_q[(qtr << 8) + col] = s;
    }
    __syncthreads();
    if (tid < NC)
        s_cnt[tid] = s_q[tid] + s_q[tid + 256] + s_q[tid + 512] + s_q[tid + 768];
    __syncthreads();

    // ---- Table via hypercube transform: warp w owns d = 2w, 2w+1 ----
    {
        const float temp = fmaxf(temp_p[0], 0.1f);
        const float r = expf(-1.0f / temp);

        float cnt[8], den[8], inv[8];
        #pragma unroll
        for (int i = 0; i < 8; i++) { cnt[i] = s_cnt[lane + (i << 5)]; den[i] = cnt[i]; }
        butterfly8(den, r);
        #pragma unroll
        for (int i = 0; i < 8; i++) inv[i] = (den[i] > 0.0f) ? (1.0f / den[i]) : 0.0f;

        float g[8];
        #pragma unroll
        for (int i = 0; i < 8; i++) g[i] = cnt[i] * vpre[i].x;
        butterfly8(g, r);
        #pragma unroll
        for (int i = 0; i < 8; i++)                  // bank (c + d)&31: conflict-free
            s_tab[(lane + (i << 5)) * PAD + (warp << 1)] = g[i] * inv[i];

        #pragma unroll
        for (int i = 0; i < 8; i++) g[i] = cnt[i] * vpre[i].y;
        butterfly8(g, r);
        #pragma unroll
        for (int i = 0; i < 8; i++)
            s_tab[(lane + (i << 5)) * PAD + (warp << 1) + 1] = g[i] * inv[i];
    }
    __syncthreads();

    // ---- Output: 4 pixels x 2 d per thread; scalar LDS + STG.128 ----
    {
        const int q4 = (tid & 31) << 2;             // 4 consecutive pixels
        const int dg = tid >> 5;                    // warp-uniform: d = 2*dg, 2*dg+1
        const int c0 = s_code[q4],     c1 = s_code[q4 + 1];
        const int c2 = s_code[q4 + 2], c3 = s_code[q4 + 3];
        float* ob = out + (((size_t)b * DV) << 12) + qbase + q4;
        #pragma unroll
        for (int j = 0; j < 2; j++) {
            const int d = (dg << 1) + j;
            float4 v = make_float4(s_tab[c0 * PAD + d], s_tab[c1 * PAD + d],
                                   s_tab[c2 * PAD + d], s_tab[c3 * PAD + d]);
            *(float4*)(ob + ((size_t)d << 12)) = v;
        }
    }
}

extern "C" void kernel_launch(void* const* d_in, const int* in_sizes, int n_in,
                              void* d_out, int out_size) {
    const float*   z    = (const float*)d_in[0];
    const uint8_t* em   = (const uint8_t*)d_in[1];
    const float*   temp = (const float*)d_in[2];
    const float*   vt   = (const float*)d_in[3];
    // d_in[4] = mask_value: multiplied by attn==0 at unmasked keys -> never contributes.
    // d_in[5] = pop_lut: replaced by r^popc tensor-product transform.
    float* out = (float*)d_out;

    // Host-side attribute set, executes immediately; first applied on the
    // pre-capture correctness call, so graph capture is unaffected.
    cudaFuncSetAttribute(gda_kernel, cudaFuncAttributeMaxDynamicSharedMemorySize, SMEM_BYTES);

    gda_kernel<<<NBLK, NTHR, SMEM_BYTES>>>(z, em, temp, vt, out);
}

// round 14
// speedup vs baseline: 1.5394x; 1.4723x over previous
#include <cuda_runtime.h>
#include <cstdint>

// Problem constants (fixed by the dataset)
#define BV 4
#define KV 8
#define NV 4096
#define DV 64
#define NC 256
#define NBLK 128     // 32 blocks/batch; 1 CTA/SM -> all resident, spin barrier safe
#define NTHR 512
#define QPB 128      // pixels whose codes/histogram this block produces

// Global scratch: fully OVERWRITTEN each launch (replay-idempotent).
__device__ float         g_part[NBLK * NC];     // per-block partial histograms
__device__ unsigned char g_codes[BV * NV];      // per-pixel codes (bytes)
__device__ unsigned int          g_bcnt[BV] = {};
__device__ volatile unsigned int g_bgen[BV] = {};

// 8-bit hypercube transform: out[c] = sum_c' in[c'] * r^popc(c^c').
// Element c at lane (c&31), register (c>>5). Bits 0-4 cross-lane, 5-7 cross-reg.
__device__ __forceinline__ void butterfly8(float g[8], float r) {
    #pragma unroll
    for (int k = 0; k < 5; k++) {
        #pragma unroll
        for (int i = 0; i < 8; i++) {
            float p = __shfl_xor_sync(0xFFFFFFFFu, g[i], 1 << k);
            g[i] = fmaf(r, p, g[i]);
        }
    }
    #pragma unroll
    for (int k = 0; k < 3; k++) {
        const int m = 1 << k;
        #pragma unroll
        for (int i = 0; i < 8; i++)
            if (!(i & m)) {
                const int j = i | m;
                const float a = g[i], b = g[j];
                g[i] = fmaf(r, b, a);
                g[j] = fmaf(r, a, b);
            }
    }
}

__global__ void __launch_bounds__(NTHR, 1) gda_kernel(
    const float* __restrict__ z, const uint8_t* __restrict__ em,
    const float* __restrict__ temp_p, const float* __restrict__ vt,
    float* __restrict__ out)
{
    __shared__ float  s_inv[NC];                 // 1/den per code (0 if empty)
    __shared__ float  s_t0[NC], s_t1[NC];        // raw transformed columns d0, d1
    __shared__ float  s_q[2 * NC];               // two half partial-sums of counts
    __shared__ float2 s_vt[NC];                  // vt[:, d0:d1] prefetched
    __shared__ __align__(16) unsigned char s_codes[NV];   // all codes of this batch
    __shared__ unsigned int s_pc[NTHR];
    __shared__ int s_cnti[NC];
    __shared__ int s_flag;

    const int tid   = threadIdx.x;
    const int b     = blockIdx.x >> 5;           // batch
    const int j     = blockIdx.x & 31;           // d-slice owner: d = 2j, 2j+1
    const int qbase = j << 7;                    // code/hist slice: 128 pixels
    const int lane  = tid & 31, warp = tid >> 5;

    if (tid < NC) s_cnti[tid] = 0;

    // ---- Probe em element width from a fixed 512B window (warp 0) ----
    // int32(0/1,LE): nonzero bytes only at offsets %4==0. byte layout with
    // ~256 random set bits in 512B: some misaligned byte nonzero w.p. ~1.
    if (tid < 32) {
        uint4 v = ((const uint4*)em)[tid];       // in-bounds either layout
        unsigned w[4] = {v.x, v.y, v.z, v.w};
        bool other = false, aligned = false;
        #pragma unroll
        for (int t = 0; t < 4; t++) {
            other   |= (w[t] & 0xFFFFFF00u) != 0u;
            aligned |= (w[t] & 0x000000FFu) != 0u;
        }
        unsigned bo = __ballot_sync(0xFFFFFFFFu, other);
        unsigned ba = __ballot_sync(0xFFFFFFFFu, aligned);
        if (tid == 0) s_flag = (bo == 0u && ba != 0u) ? 1 : 0;
    }

    // ---- Codes for OWN 128 pixels: 4 threads/pixel, 2 bit-planes each ----
    {
        const float* zb = z + ((size_t)b * KV) * NV + qbase;
        const int p  = tid & (QPB - 1);
        const int k0 = (tid >> 7) << 1;          // 0,2,4,6
        s_pc[tid] = (unsigned)(zb[k0 * NV + p]       > 0.5f) << k0
                  | (unsigned)(zb[(k0 + 1) * NV + p] > 0.5f) << (k0 + 1);
    }

    // ---- Prefetch my two vt columns + temperature (independent of barrier) ----
    if (tid < NC) s_vt[tid] = ((const float2*)vt)[(tid << 5) + j];
    const float temp = fmaxf(temp_p[0], 0.1f);
    const float rw = expf(-1.0f / temp);
    __syncthreads();

    // ---- Combine code bits; publish codes; local masked histogram ----
    const bool is_i32 = (s_flag != 0);
    if (tid < QPB) {
        const unsigned code = s_pc[tid] | s_pc[tid + 128] |
                              s_pc[tid + 256] | s_pc[tid + 384];
        g_codes[(b << 12) + qbase + tid] = (unsigned char)code;
        const size_t mi = (size_t)(b * NV + qbase + tid) * (is_i32 ? 4 : 1);
        if (em[mi] != 0) atomicAdd(&s_cnti[code], 1);
    }
    __syncthreads();
    if (tid < NC)
        g_part[(blockIdx.x << 8) + tid] = (float)s_cnti[tid];
    __syncthreads();

    // ---- Per-batch barrier (32-way): codes + partials of batch b visible ----
    if (tid == 0) {
        __threadfence();                         // release (block's stores ordered by sync above)
        unsigned g = g_bgen[b];
        if (atomicAdd(&g_bcnt[b], 1u) == 31u) {
            g_bcnt[b] = 0;
            __threadfence();
            g_bgen[b] = g + 1;
        } else {
            while (g_bgen[b] == g) { }
        }
        __threadfence();                         // acquire
    }
    __syncthreads();

    // ---- Post-barrier loads (high MLP): all 4096 codes + partial half-sums ----
    {
        const uint32_t* gc = (const uint32_t*)g_codes + ((size_t)b << 10);
        ((uint32_t*)s_codes)[tid]       = __ldcg(&gc[tid]);
        ((uint32_t*)s_codes)[tid + 512] = __ldcg(&gc[tid + 512]);
    }
    {
        const int col = tid & 255, half = tid >> 8;
        const float* gp = g_part + (((b << 5) + (half << 4)) << 8) + col;
        float s = 0.0f;
        #pragma unroll
        for (int t = 0; t < 16; t++) s += __ldcg(gp + (t << 8));
        s_q[(half << 8) + col] = s;
    }
    __syncthreads();

    // ---- Three butterflies, one warp each (den -> inv, column d0, column d1) ----
    if (warp < 3) {
        float cnt[8], g[8];
        #pragma unroll
        for (int i = 0; i < 8; i++) {
            const int c = lane + (i << 5);
            cnt[i] = s_q[c] + s_q[c + 256];
        }
        if (warp == 0) {
            #pragma unroll
            for (int i = 0; i < 8; i++) g[i] = cnt[i];
            butterfly8(g, rw);
            #pragma unroll
            for (int i = 0; i < 8; i++)
                s_inv[lane + (i << 5)] = (g[i] > 0.0f) ? (1.0f / g[i]) : 0.0f;
        } else if (warp == 1) {
            #pragma unroll
            for (int i = 0; i < 8; i++) g[i] = cnt[i] * s_vt[lane + (i << 5)].x;
            butterfly8(g, rw);
            #pragma unroll
            for (int i = 0; i < 8; i++) s_t0[lane + (i << 5)] = g[i];
        } else {
            #pragma unroll
            for (int i = 0; i < 8; i++) g[i] = cnt[i] * s_vt[lane + (i << 5)].y;
            butterfly8(g, rw);
            #pragma unroll
            for (int i = 0; i < 8; i++) s_t1[lane + (i << 5)] = g[i];
        }
    }
    __syncthreads();

    // ---- Write my 2 output planes for ALL 4096 pixels (coalesced STG.128) ----
    {
        float* p0 = out + (((size_t)(b * DV + (j << 1))) << 12);
        float* p1 = p0 + NV;
        #pragma unroll
        for (int ch = 0; ch < 2; ch++) {
            const int q4 = (ch << 11) + (tid << 2);      // 4 consecutive pixels
            const uchar4 cd = *(const uchar4*)&s_codes[q4];
            const float i0 = s_inv[cd.x], i1 = s_inv[cd.y];
            const float i2 = s_inv[cd.z], i3 = s_inv[cd.w];
            float4 v0 = make_float4(s_t0[cd.x] * i0, s_t0[cd.y] * i1,
                                    s_t0[cd.z] * i2, s_t0[cd.w] * i3);
            float4 v1 = make_float4(s_t1[cd.x] * i0, s_t1[cd.y] * i1,
                                    s_t1[cd.z] * i2, s_t1[cd.w] * i3);
            *(float4*)(p0 + q4) = v0;
            *(float4*)(p1 + q4) = v1;
        }
    }
}

extern "C" void kernel_launch(void* const* d_in, const int* in_sizes, int n_in,
                              void* d_out, int out_size) {
    const float*   z    = (const float*)d_in[0];
    const uint8_t* em   = (const uint8_t*)d_in[1];
    const float*   temp = (const float*)d_in[2];
    const float*   vt   = (const float*)d_in[3];
    // d_in[4] = mask_value: multiplied by attn==0 at unmasked keys -> never contributes.
    // d_in[5] = pop_lut: replaced by r^popc tensor-product transform.
    float* out = (float*)d_out;

    gda_kernel<<<NBLK, NTHR>>>(z, em, temp, vt, out);
}

// round 15
// speedup vs baseline: 1.9483x; 1.2657x over previous
#include <cuda_runtime.h>
#include <cstdint>

// Problem constants (fixed by the dataset)
#define BV 4
#define KV 8
#define NV 4096
#define DV 64
#define NC 256
#define NBLK 128     // 32 blocks/batch
#define QPB 128      // pixels whose codes/histogram each A-block produces

// Global scratch: fully OVERWRITTEN each launch (replay-idempotent, no zeroing).
__device__ float         g_part[NBLK * NC];     // per-block partial histograms
__device__ unsigned char g_codes[BV * NV];      // per-pixel codes (bytes)

// 8-bit hypercube transform: out[c] = sum_c' in[c'] * r^popc(c^c').
// Element c at lane (c&31), register (c>>5). Bits 0-4 cross-lane, 5-7 cross-reg.
__device__ __forceinline__ void butterfly8(float g[8], float r) {
    #pragma unroll
    for (int k = 0; k < 5; k++) {
        #pragma unroll
        for (int i = 0; i < 8; i++) {
            float p = __shfl_xor_sync(0xFFFFFFFFu, g[i], 1 << k);
            g[i] = fmaf(r, p, g[i]);
        }
    }
    #pragma unroll
    for (int k = 0; k < 3; k++) {
        const int m = 1 << k;
        #pragma unroll
        for (int i = 0; i < 8; i++)
            if (!(i & m)) {
                const int j = i | m;
                const float a = g[i], b = g[j];
                g[i] = fmaf(r, b, a);
                g[j] = fmaf(r, a, b);
            }
    }
}

// ---------- Kernel A: codes + masked partial histograms (no sync w/ peers) ----------
__global__ void __launch_bounds__(256, 1) gda_codes(
    const float* __restrict__ z, const uint8_t* __restrict__ em)
{
    __shared__ unsigned s_pc[256];
    __shared__ int s_cnti[NC];
    __shared__ __align__(4) unsigned char s_cb[QPB];
    __shared__ int s_flag;

    const int tid   = threadIdx.x;
    const int b     = blockIdx.x >> 5;
    const int qbase = (blockIdx.x & 31) << 7;

    s_cnti[tid] = 0;

    // Probe em element width from a fixed 512B window (warp 0).
    // int32(0/1,LE): nonzero bytes only at offsets %4==0. byte layout with
    // ~256 random set bits in 512B: some misaligned byte nonzero w.p. ~1.
    if (tid < 32) {
        uint4 v = ((const uint4*)em)[tid];          // in-bounds either layout
        unsigned w[4] = {v.x, v.y, v.z, v.w};
        bool other = false, aligned = false;
        #pragma unroll
        for (int t = 0; t < 4; t++) {
            other   |= (w[t] & 0xFFFFFF00u) != 0u;
            aligned |= (w[t] & 0x000000FFu) != 0u;
        }
        unsigned bo = __ballot_sync(0xFFFFFFFFu, other);
        unsigned ba = __ballot_sync(0xFFFFFFFFu, aligned);
        if (tid == 0) s_flag = (bo == 0u && ba != 0u) ? 1 : 0;
    }

    // Codes: 2 threads/pixel, 4 bit-planes each (coalesced 512B per plane).
    {
        const float* zb = z + ((size_t)b * KV) * NV + qbase;
        const int p  = tid & (QPB - 1);
        const int k0 = (tid >> 7) << 2;             // 0 or 4
        unsigned pc = 0;
        #pragma unroll
        for (int t = 0; t < 4; t++)
            pc |= (unsigned)(zb[(k0 + t) * NV + p] > 0.5f) << (k0 + t);
        s_pc[tid] = pc;
    }
    __syncthreads();

    const bool is_i32 = (s_flag != 0);
    if (tid < QPB) {
        const unsigned code = s_pc[tid] | s_pc[tid + 128];
        s_cb[tid] = (unsigned char)code;
        const size_t mi = (size_t)(b * NV + qbase + tid) * (is_i32 ? 4 : 1);
        if (em[mi] != 0) atomicAdd(&s_cnti[code], 1);
    }
    __syncthreads();

    if (tid < 32)
        ((uint32_t*)&g_codes[(b << 12) + qbase])[tid] = ((const uint32_t*)s_cb)[tid];
    g_part[(blockIdx.x << 8) + tid] = (float)s_cnti[tid];
}

// ---------- Kernel B: table slice via butterfly + 2 output planes ----------
__global__ void __launch_bounds__(512, 1) gda_table_out(
    const float* __restrict__ temp_p, const float* __restrict__ vt,
    float* __restrict__ out)
{
    __shared__ float  s_inv[NC];                    // 1/den per code (0 if empty)
    __shared__ float  s_t0[NC], s_t1[NC];           // transformed columns d0, d1
    __shared__ float  s_q[2 * NC];                  // two half partial-sums
    __shared__ float2 s_vt[NC];                     // vt[:, d0:d1]
    __shared__ __align__(16) unsigned char s_codes[NV];

    const int tid  = threadIdx.x;
    const int b    = blockIdx.x >> 5;               // batch
    const int j    = blockIdx.x & 31;               // d-slice owner: d = 2j, 2j+1
    const int lane = tid & 31, warp = tid >> 5;

    // High-MLP loads: all 4096 codes + my vt columns + partial half-sums.
    {
        const uint32_t* gc = (const uint32_t*)g_codes + ((size_t)b << 10);
        ((uint32_t*)s_codes)[tid]       = __ldcg(&gc[tid]);
        ((uint32_t*)s_codes)[tid + 512] = __ldcg(&gc[tid + 512]);
    }
    if (tid < NC) s_vt[tid] = ((const float2*)vt)[(tid << 5) + j];
    {
        const int col = tid & 255, half = tid >> 8;
        const float* gp = g_part + (((b << 5) + (half << 4)) << 8) + col;
        float s = 0.0f;
        #pragma unroll
        for (int t = 0; t < 16; t++) s += __ldcg(gp + (t << 8));
        s_q[(half << 8) + col] = s;
    }
    const float temp = fmaxf(temp_p[0], 0.1f);
    const float rw = expf(-1.0f / temp);
    __syncthreads();

    // Three butterflies, one warp each (den -> inv, column d0, column d1).
    if (warp < 3) {
        float cnt[8], g[8];
        #pragma unroll
        for (int i = 0; i < 8; i++) {
            const int c = lane + (i << 5);
            cnt[i] = s_q[c] + s_q[c + 256];
        }
        if (warp == 0) {
            #pragma unroll
            for (int i = 0; i < 8; i++) g[i] = cnt[i];
            butterfly8(g, rw);
            #pragma unroll
            for (int i = 0; i < 8; i++)
                s_inv[lane + (i << 5)] = (g[i] > 0.0f) ? (1.0f / g[i]) : 0.0f;
        } else if (warp == 1) {
            #pragma unroll
            for (int i = 0; i < 8; i++) g[i] = cnt[i] * s_vt[lane + (i << 5)].x;
            butterfly8(g, rw);
            #pragma unroll
            for (int i = 0; i < 8; i++) s_t0[lane + (i << 5)] = g[i];
        } else {
            #pragma unroll
            for (int i = 0; i < 8; i++) g[i] = cnt[i] * s_vt[lane + (i << 5)].y;
            butterfly8(g, rw);
            #pragma unroll
            for (int i = 0; i < 8; i++) s_t1[lane + (i << 5)] = g[i];
        }
    }
    __syncthreads();

    // Write my 2 output planes for ALL 4096 pixels (coalesced STG.128).
    {
        float* p0 = out + (((size_t)(b * DV + (j << 1))) << 12);
        float* p1 = p0 + NV;
        #pragma unroll
        for (int ch = 0; ch < 2; ch++) {
            const int q4 = (ch << 11) + (tid << 2);     // 4 consecutive pixels
            const uchar4 cd = *(const uchar4*)&s_codes[q4];
            const float i0 = s_inv[cd.x], i1 = s_inv[cd.y];
            const float i2 = s_inv[cd.z], i3 = s_inv[cd.w];
            float4 v0 = make_float4(s_t0[cd.x] * i0, s_t0[cd.y] * i1,
                                    s_t0[cd.z] * i2, s_t0[cd.w] * i3);
            float4 v1 = make_float4(s_t1[cd.x] * i0, s_t1[cd.y] * i1,
                                    s_t1[cd.z] * i2, s_t1[cd.w] * i3);
            *(float4*)(p0 + q4) = v0;
            *(float4*)(p1 + q4) = v1;
        }
    }
}

extern "C" void kernel_launch(void* const* d_in, const int* in_sizes, int n_in,
                              void* d_out, int out_size) {
    const float*   z    = (const float*)d_in[0];
    const uint8_t* em   = (const uint8_t*)d_in[1];
    const float*   temp = (const float*)d_in[2];
    const float*   vt   = (const float*)d_in[3];
    // d_in[4] = mask_value: multiplied by attn==0 at unmasked keys -> never contributes.
    // d_in[5] = pop_lut: replaced by r^popc tensor-product transform.
    float* out = (float*)d_out;

    // Same-stream launches -> graph edge provides ordering + visibility
    // (replaces the in-kernel spin barrier entirely).
    gda_codes    <<<NBLK, 256>>>(z, em);
    gda_table_out<<<NBLK, 512>>>(temp, vt, out);
}